// round 10
// baseline (speedup 1.0000x reference)
#include <cuda_runtime.h>
#include <cuda_fp16.h>
#include <math.h>
#include <stdint.h>

#define BS    32
#define NMM   256
#define NV    196
#define NA    60
#define NKV   256
#define DIM   768
#define HEADS 12
#define HD    64
#define KVDIM 1536

#define OUT_ELEMS  (BS * NMM * DIM)
#define ATTN_ELEMS (BS * HEADS * NMM * NKV)
#define M_ROWS     (BS * NMM)
#define NBH        (BS * HEADS)

// ---------------------------------------------------------------------------
// Scratch
// ---------------------------------------------------------------------------
__device__ __half g_xmm_h[M_ROWS * DIM];
__device__ __half g_xmm_l[M_ROWS * DIM];
__device__ __half g_xsrc_h[M_ROWS * DIM];
__device__ __half g_WqT_h[DIM * DIM];
__device__ __half g_WkvT_h[KVDIM * DIM];
__device__ __half g_WpT_h[DIM * DIM];

__device__ __half g_Qh[NBH * NMM * HD];
__device__ __half g_Ql[NBH * NMM * HD];
__device__ __half g_Kh[NBH * NKV * HD];
__device__ __half g_Vh[NBH * NKV * HD];
__device__ __half g_Oh[M_ROWS * DIM];
__device__ float g_attn_fallback[ATTN_ELEMS];

// ---------------------------------------------------------------------------
// PTX helpers
// ---------------------------------------------------------------------------
__device__ __forceinline__ uint32_t smem_u32(const void* p) {
    uint32_t a;
    asm("{ .reg .u64 t; cvta.to.shared.u64 t, %1; cvt.u32.u64 %0, t; }" : "=r"(a) : "l"(p));
    return a;
}
__device__ __forceinline__ void cp_async16(uint32_t sa, const void* gp) {
    asm volatile("cp.async.cg.shared.global [%0], [%1], 16;" :: "r"(sa), "l"(gp) : "memory");
}
__device__ __forceinline__ void cp_commit() {
    asm volatile("cp.async.commit_group;" ::: "memory");
}
template <int N>
__device__ __forceinline__ void cp_wait() {
    asm volatile("cp.async.wait_group %0;" :: "n"(N) : "memory");
}
__device__ __forceinline__ void ldsm4(uint32_t& r0, uint32_t& r1, uint32_t& r2, uint32_t& r3,
                                      uint32_t addr) {
    asm volatile("ldmatrix.sync.aligned.m8n8.x4.shared.b16 {%0,%1,%2,%3}, [%4];"
                 : "=r"(r0), "=r"(r1), "=r"(r2), "=r"(r3) : "r"(addr));
}
__device__ __forceinline__ void ldsm4t(uint32_t& r0, uint32_t& r1, uint32_t& r2, uint32_t& r3,
                                       uint32_t addr) {
    asm volatile("ldmatrix.sync.aligned.m8n8.x4.trans.shared.b16 {%0,%1,%2,%3}, [%4];"
                 : "=r"(r0), "=r"(r1), "=r"(r2), "=r"(r3) : "r"(addr));
}
__device__ __forceinline__ void mma16816(float* c, const uint32_t* a, uint32_t b0, uint32_t b1) {
    asm volatile(
        "mma.sync.aligned.m16n8k16.row.col.f32.f16.f16.f32 "
        "{%0,%1,%2,%3}, {%4,%5,%6,%7}, {%8,%9}, {%0,%1,%2,%3};"
        : "+f"(c[0]), "+f"(c[1]), "+f"(c[2]), "+f"(c[3])
        : "r"(a[0]), "r"(a[1]), "r"(a[2]), "r"(a[3]), "r"(b0), "r"(b1));
}

__device__ __forceinline__ void pack_hl(float f0, float f1, uint32_t& h, uint32_t& l) {
    __half h0 = __float2half_rn(f0);
    __half h1 = __float2half_rn(f1);
    __half l0 = __float2half_rn(f0 - __half2float(h0));
    __half l1 = __float2half_rn(f1 - __half2float(h1));
    __half2 hp = __halves2half2(h0, h1);
    __half2 lp = __halves2half2(l0, l1);
    h = *reinterpret_cast<uint32_t*>(&hp);
    l = *reinterpret_cast<uint32_t*>(&lp);
}
__device__ __forceinline__ uint32_t pack_h(float f0, float f1) {
    __half2 hp = __halves2half2(__float2half_rn(f0), __float2half_rn(f1));
    return *reinterpret_cast<uint32_t*>(&hp);
}

// ---------------------------------------------------------------------------
// Fused input-prep + weight transposes (one launch, disjoint block ranges).
// xmm -> hi+lo; xsrc -> hi only (KV projection is 1-term now).
// ---------------------------------------------------------------------------
__device__ __forceinline__ void split4(float4 v, uint2& hv, uint2& lv) {
    uint32_t h0, l0, h1, l1;
    pack_hl(v.x, v.y, h0, l0);
    pack_hl(v.z, v.w, h1, l1);
    hv.x = h0; hv.y = h1; lv.x = l0; lv.y = l1;
}
__device__ __forceinline__ uint2 round4(float4 v) {
    uint2 hv;
    hv.x = pack_h(v.x, v.y);
    hv.y = pack_h(v.z, v.w);
    return hv;
}

#define N4 (M_ROWS * DIM / 4)
#define PREP_BLOCKS (2 * N4 / 256)          // 12288
#define TR_BLOCKS   (96 * 24)               // 2304

__global__ __launch_bounds__(256)
void prep_all_kernel(const float4* __restrict__ xmm,
                     const float* __restrict__ xv, const float* __restrict__ xa,
                     uint2* __restrict__ xmm_h, uint2* __restrict__ xmm_l,
                     uint2* __restrict__ xsrc_h,
                     const float* __restrict__ Wq, const float* __restrict__ Wkv,
                     const float* __restrict__ Wp,
                     __half* __restrict__ WqT, __half* __restrict__ WkvT,
                     __half* __restrict__ WpT) {
    const int bx = blockIdx.x;
    if (bx < PREP_BLOCKS) {
        int i = bx * 256 + threadIdx.x;
        if (i < N4) {
            uint2 hv, lv;
            split4(xmm[i], hv, lv);
            xmm_h[i] = hv;
            xmm_l[i] = lv;
        } else {
            i -= N4;
            const int C4 = DIM / 4;
            int row = i / C4;
            int c4  = i - row * C4;
            int b = row >> 8;
            int r = row & 255;
            const float4* src = (r < NV)
                ? reinterpret_cast<const float4*>(xv + (size_t)(b * NV + r) * DIM)
                : reinterpret_cast<const float4*>(xa + (size_t)(b * NA + (r - NV)) * DIM);
            xsrc_h[i] = round4(src[c4]);
        }
    } else {
        __shared__ float t[32][33];
        int b2 = bx - PREP_BLOCKS;
        int nbx = b2 % 96;
        int ky  = b2 / 96;
        const float* W; __half* T; int N; int nb;
        if (nbx < 24)      { W = Wq;  T = WqT;  N = DIM;   nb = nbx; }
        else if (nbx < 72) { W = Wkv; T = WkvT; N = KVDIM; nb = nbx - 24; }
        else               { W = Wp;  T = WpT;  N = DIM;   nb = nbx - 72; }
        int k0 = ky * 32, n0 = nb * 32;
        int x = threadIdx.x & 31, y = threadIdx.x >> 5;
        #pragma unroll
        for (int i = 0; i < 32; i += 8)
            t[y + i][x] = W[(size_t)(k0 + y + i) * N + n0 + x];
        __syncthreads();
        #pragma unroll
        for (int i = 0; i < 32; i += 8)
            T[(size_t)(n0 + y + i) * DIM + k0 + x] = __float2half_rn(t[x][y + i]);
    }
}

// ---------------------------------------------------------------------------
// Merged Q + KV projection kernel.
// blockIdx.x < 6  : Q = (xmm_h + xmm_l) @ WqT  -> Qh/Ql split epi (2-term)
// blockIdx.x >= 6 : KV = xsrc_h @ WkvT        -> Kh / Vh epi (1-term)
// ---------------------------------------------------------------------------
#define GK 768
#define PAD_ROW 80
#define ARR_BYTES (128 * PAD_ROW)
#define STAGE_BYTES (3 * ARR_BYTES)
#define QKV_SMEM (3 * STAGE_BYTES)

__global__ __launch_bounds__(256, 2)
void qkv_proj_kernel(const __half* __restrict__ Amh, const __half* __restrict__ Aml,
                     const __half* __restrict__ QT,
                     const __half* __restrict__ Ash, const __half* __restrict__ KVT,
                     __half* __restrict__ QhO, __half* __restrict__ QlO,
                     __half* __restrict__ KhO, __half* __restrict__ VhO) {
    extern __shared__ char smem[];
    const uint32_t sb = smem_u32(smem);

    const int tid  = threadIdx.x;
    const int lane = tid & 31;
    const int wid  = tid >> 5;
    const int wr   = wid >> 2;
    const int wc   = wid & 3;
    const int m0   = blockIdx.y * 128;
    const bool isQ = (blockIdx.x < 6);
    const int n0   = isQ ? blockIdx.x * 128 : (blockIdx.x - 6) * 128;

    const __half* base0 = (isQ ? Amh : Ash) + (size_t)m0 * GK;
    const __half* base1 = Aml + (size_t)m0 * GK;               // only used for Q
    const __half* base2 = (isQ ? QT : KVT) + (size_t)n0 * GK;

    auto issue_stage = [&](int chunk, int s) {
        const int k0 = chunk << 5;
        const uint32_t sbase = sb + s * STAGE_BYTES;
        #pragma unroll
        for (int it = 0; it < 6; it++) {
            const int arr = it >> 1;
            if (arr == 1 && !isQ) continue;
            const int j   = tid + (it & 1) * 256;
            const int row = j >> 2;
            const int q   = j & 3;
            const __half* gp =
                (arr == 0 ? base0 : arr == 1 ? base1 : base2)
                + (size_t)row * GK + k0 + q * 8;
            cp_async16(sbase + arr * ARR_BYTES + row * PAD_ROW + q * 16, gp);
        }
        cp_commit();
    };

    float c[4][4][4];
    #pragma unroll
    for (int i = 0; i < 4; i++)
        #pragma unroll
        for (int j = 0; j < 4; j++)
            #pragma unroll
            for (int k = 0; k < 4; k++) c[i][j][k] = 0.0f;

    const int lr   = lane & 15;
    const int lc16 = (lane >> 4) * 16;

    issue_stage(0, 0);
    issue_stage(1, 1);

    const int nchunks = GK / 32;  // 24
    for (int i = 0; i < nchunks; i++) {
        if (i + 1 < nchunks) cp_wait<1>(); else cp_wait<0>();
        __syncthreads();
        if (i + 2 < nchunks) issue_stage(i + 2, (i + 2) % 3);

        const uint32_t st = sb + (i % 3) * STAGE_BYTES;
        const uint32_t aH_base = st + 0 * ARR_BYTES + (wr * 64 + lr) * PAD_ROW + lc16;
        const uint32_t aL_base = st + 1 * ARR_BYTES + (wr * 64 + lr) * PAD_ROW + lc16;
        const uint32_t bH_base = st + 2 * ARR_BYTES + (wc * 32 + lr) * PAD_ROW + lc16;

        #pragma unroll
        for (int kk = 0; kk < 2; kk++) {
            const uint32_t ko = kk * 32;
            uint32_t bh[4][2];
            #pragma unroll
            for (int bt = 0; bt < 2; bt++) {
                uint32_t r0, r1, r2, r3;
                ldsm4(r0, r1, r2, r3, bH_base + bt * 16 * PAD_ROW + ko);
                bh[bt * 2 + 0][0] = r0; bh[bt * 2 + 0][1] = r2;
                bh[bt * 2 + 1][0] = r1; bh[bt * 2 + 1][1] = r3;
            }
            #pragma unroll
            for (int mt = 0; mt < 4; mt++) {
                uint32_t aH[4], aL[4];
                ldsm4(aH[0], aH[1], aH[2], aH[3], aH_base + mt * 16 * PAD_ROW + ko);
                if (isQ)
                    ldsm4(aL[0], aL[1], aL[2], aL[3], aL_base + mt * 16 * PAD_ROW + ko);
                #pragma unroll
                for (int ni = 0; ni < 4; ni++) mma16816(c[mt][ni], aH, bh[ni][0], bh[ni][1]);
                if (isQ) {
                    #pragma unroll
                    for (int ni = 0; ni < 4; ni++) mma16816(c[mt][ni], aL, bh[ni][0], bh[ni][1]);
                }
            }
        }
    }

    // Epilogue
    const int crow0 = m0 + wr * 64 + (lane >> 2);
    const int ccol0 = n0 + wc * 32 + (lane & 3) * 2;
    #pragma unroll
    for (int mt = 0; mt < 4; mt++) {
        #pragma unroll
        for (int ni = 0; ni < 4; ni++) {
            const int cc = ccol0 + ni * 8;
            const float* cf = c[mt][ni];
            const int r0 = crow0 + mt * 16;
            const int r1 = r0 + 8;
            if (isQ) {
                const int h = cc >> 6, d = cc & 63;
                #pragma unroll
                for (int s = 0; s < 2; s++) {
                    const int r = s ? r1 : r0;
                    const int b = r >> 8, q = r & 255;
                    size_t idx = (((size_t)(b * HEADS + h)) * NMM + q) * HD + d;
                    uint32_t hh, ll;
                    pack_hl(cf[s * 2], cf[s * 2 + 1], hh, ll);
                    *reinterpret_cast<uint32_t*>(QhO + idx) = hh;
                    *reinterpret_cast<uint32_t*>(QlO + idx) = ll;
                }
            } else {
                const bool isK = (cc < DIM);
                const int ccl = isK ? cc : cc - DIM;
                const int h = ccl >> 6, d = ccl & 63;
                __half* Hd = isK ? KhO : VhO;
                #pragma unroll
                for (int s = 0; s < 2; s++) {
                    const int r = s ? r1 : r0;
                    const int b = r >> 8, t = r & 255;
                    size_t idx = (((size_t)(b * HEADS + h)) * NKV + t) * HD + d;
                    *reinterpret_cast<uint32_t*>(Hd + idx) = pack_h(cf[s * 2], cf[s * 2 + 1]);
                }
            }
        }
    }
}

// ---------------------------------------------------------------------------
// Lean out-projection: out = Oh @ WpT + bias (1-term). 2-array stages, 3 of
// them -> 61 KB smem; __launch_bounds__(256,3) -> 3 CTAs/SM, grid 384 = 1 wave.
// ---------------------------------------------------------------------------
#define OSTAGE_BYTES (2 * ARR_BYTES)            // 20480
#define OPROJ_SMEM (3 * OSTAGE_BYTES)           // 61440

__global__ __launch_bounds__(256, 3)
void out_proj_kernel(const __half* __restrict__ Ah, const __half* __restrict__ BT,
                     const float* __restrict__ bias, float* __restrict__ C) {
    extern __shared__ char smem[];
    const uint32_t sb = smem_u32(smem);

    const int tid  = threadIdx.x;
    const int lane = tid & 31;
    const int wid  = tid >> 5;
    const int wr   = wid >> 2;
    const int wc   = wid & 3;
    const int m0   = blockIdx.y * 128;
    const int n0   = blockIdx.x * 128;

    const __half* base0 = Ah + (size_t)m0 * GK;
    const __half* base2 = BT + (size_t)n0 * GK;

    auto issue_stage = [&](int chunk, int s) {
        const int k0 = chunk << 5;
        const uint32_t sbase = sb + s * OSTAGE_BYTES;
        #pragma unroll
        for (int it = 0; it < 4; it++) {
            const int arr = it >> 1;
            const int j   = tid + (it & 1) * 256;
            const int row = j >> 2;
            const int q   = j & 3;
            const __half* gp = (arr == 0 ? base0 : base2) + (size_t)row * GK + k0 + q * 8;
            cp_async16(sbase + arr * ARR_BYTES + row * PAD_ROW + q * 16, gp);
        }
        cp_commit();
    };

    float c[4][4][4];
    #pragma unroll
    for (int i = 0; i < 4; i++)
        #pragma unroll
        for (int j = 0; j < 4; j++)
            #pragma unroll
            for (int k = 0; k < 4; k++) c[i][j][k] = 0.0f;

    const int lr   = lane & 15;
    const int lc16 = (lane >> 4) * 16;

    issue_stage(0, 0);
    issue_stage(1, 1);

    const int nchunks = GK / 32;
    for (int i = 0; i < nchunks; i++) {
        if (i + 1 < nchunks) cp_wait<1>(); else cp_wait<0>();
        __syncthreads();
        if (i + 2 < nchunks) issue_stage(i + 2, (i + 2) % 3);

        const uint32_t st = sb + (i % 3) * OSTAGE_BYTES;
        const uint32_t aH_base = st + 0 * ARR_BYTES + (wr * 64 + lr) * PAD_ROW + lc16;
        const uint32_t bH_base = st + 1 * ARR_BYTES + (wc * 32 + lr) * PAD_ROW + lc16;

        #pragma unroll
        for (int kk = 0; kk < 2; kk++) {
            const uint32_t ko = kk * 32;
            uint32_t bh[4][2];
            #pragma unroll
            for (int bt = 0; bt < 2; bt++) {
                uint32_t r0, r1, r2, r3;
                ldsm4(r0, r1, r2, r3, bH_base + bt * 16 * PAD_ROW + ko);
                bh[bt * 2 + 0][0] = r0; bh[bt * 2 + 0][1] = r2;
                bh[bt * 2 + 1][0] = r1; bh[bt * 2 + 1][1] = r3;
            }
            #pragma unroll
            for (int mt = 0; mt < 4; mt++) {
                uint32_t aH[4];
                ldsm4(aH[0], aH[1], aH[2], aH[3], aH_base + mt * 16 * PAD_ROW + ko);
                #pragma unroll
                for (int ni = 0; ni < 4; ni++) mma16816(c[mt][ni], aH, bh[ni][0], bh[ni][1]);
            }
        }
    }

    const int crow0 = m0 + wr * 64 + (lane >> 2);
    const int ccol0 = n0 + wc * 32 + (lane & 3) * 2;
    #pragma unroll
    for (int mt = 0; mt < 4; mt++) {
        #pragma unroll
        for (int ni = 0; ni < 4; ni++) {
            const int cc = ccol0 + ni * 8;
            const float* cf = c[mt][ni];
            const int r0 = crow0 + mt * 16;
            float b0 = bias[cc], b1 = bias[cc + 1];
            float2 v0 = { cf[0] + b0, cf[1] + b1 };
            float2 v1 = { cf[2] + b0, cf[3] + b1 };
            *reinterpret_cast<float2*>(C + (size_t)r0 * DIM + cc) = v0;
            *reinterpret_cast<float2*>(C + (size_t)(r0 + 8) * DIM + cc) = v1;
        }
    }
}

// ---------------------------------------------------------------------------
// Fused attention: QK + softmax + attn write + AV.
// CTA: 64 q rows, 128 threads (4 warps); warp = 16 q rows x 256 tokens.
// ---------------------------------------------------------------------------
#define FA_PAD 144
#define FA_QH 0
#define FA_QL (64 * FA_PAD)
#define FA_K  (2 * 64 * FA_PAD)
#define FA_V  (FA_K + 256 * FA_PAD)
#define FA_SMEM (FA_V + 256 * FA_PAD)     // 92160

__global__ __launch_bounds__(128, 2)
void fused_attn_kernel(const __half* __restrict__ Qh, const __half* __restrict__ Ql,
                       const __half* __restrict__ Kh, const __half* __restrict__ Vh,
                       float* __restrict__ attnF, __half* __restrict__ Oh,
                       int writeAttn) {
    extern __shared__ char smem[];
    const uint32_t sb = smem_u32(smem);
    const int bh = blockIdx.y;
    const int q0 = blockIdx.x * 64;
    const int tid  = threadIdx.x;
    const int lane = tid & 31;
    const int wid  = tid >> 5;

    const __half* gQh = Qh + ((size_t)bh * NMM + q0) * HD;
    const __half* gQl = Ql + ((size_t)bh * NMM + q0) * HD;
    const __half* gKh = Kh + (size_t)bh * NKV * HD;
    const __half* gVh = Vh + (size_t)bh * NKV * HD;

    for (int idx = tid; idx < 512; idx += 128) {
        int row = idx >> 3, cq = idx & 7;
        cp_async16(sb + FA_QH + row * FA_PAD + cq * 16, gQh + row * HD + cq * 8);
        cp_async16(sb + FA_QL + row * FA_PAD + cq * 16, gQl + row * HD + cq * 8);
    }
    for (int idx = tid; idx < 2048; idx += 128) {
        int row = idx >> 3, cq = idx & 7;
        cp_async16(sb + FA_K + row * FA_PAD + cq * 16, gKh + row * HD + cq * 8);
    }
    cp_commit();
    for (int idx = tid; idx < 2048; idx += 128) {
        int row = idx >> 3, cq = idx & 7;
        cp_async16(sb + FA_V + row * FA_PAD + cq * 16, gVh + row * HD + cq * 8);
    }
    cp_commit();

    cp_wait<1>();
    __syncthreads();

    const int lr = lane & 15;
    const int lc16 = (lane >> 4) * 16;
    const int rowbase = wid * 16;

    float c[32][4];
    #pragma unroll
    for (int j = 0; j < 32; j++)
        #pragma unroll
        for (int k = 0; k < 4; k++) c[j][k] = 0.0f;

    #pragma unroll
    for (int kk = 0; kk < 4; kk++) {
        const uint32_t ko = kk * 32;
        uint32_t aH[4], aL[4];
        const uint32_t ab = sb + FA_QH + (rowbase + lr) * FA_PAD + ko + lc16;
        ldsm4(aH[0], aH[1], aH[2], aH[3], ab);
        ldsm4(aL[0], aL[1], aL[2], aL[3], ab + FA_QL);
        #pragma unroll
        for (int tb = 0; tb < 16; tb++) {
            const uint32_t bb = sb + FA_K + (tb * 16 + lr) * FA_PAD + ko + lc16;
            uint32_t h0, h1, h2, h3;
            ldsm4(h0, h1, h2, h3, bb);
            mma16816(c[tb * 2],     aH, h0, h2);
            mma16816(c[tb * 2],     aL, h0, h2);
            mma16816(c[tb * 2 + 1], aH, h1, h3);
            mma16816(c[tb * 2 + 1], aL, h1, h3);
        }
    }

    const float scale = 0.125f;
    #pragma unroll
    for (int s2 = 0; s2 < 2; s2++) {
        float m = -INFINITY;
        #pragma unroll
        for (int nt = 0; nt < 32; nt++) {
            m = fmaxf(m, c[nt][s2 * 2]);
            m = fmaxf(m, c[nt][s2 * 2 + 1]);
        }
        m = fmaxf(m, __shfl_xor_sync(0xffffffffu, m, 1));
        m = fmaxf(m, __shfl_xor_sync(0xffffffffu, m, 2));
        float sum = 0.0f;
        #pragma unroll
        for (int nt = 0; nt < 32; nt++) {
            float e0 = __expf((c[nt][s2 * 2]     - m) * scale);
            float e1 = __expf((c[nt][s2 * 2 + 1] - m) * scale);
            c[nt][s2 * 2]     = e0;
            c[nt][s2 * 2 + 1] = e1;
            sum += e0 + e1;
        }
        sum += __shfl_xor_sync(0xffffffffu, sum, 1);
        sum += __shfl_xor_sync(0xffffffffu, sum, 2);
        float inv = 1.0f / sum;
        #pragma unroll
        for (int nt = 0; nt < 32; nt++) {
            c[nt][s2 * 2]     *= inv;
            c[nt][s2 * 2 + 1] *= inv;
        }
    }

    if (writeAttn) {
        const int r  = lane >> 2;
        const int c0 = (lane & 3) * 2;
        float* rowp0 = attnF + ((size_t)bh * NMM + q0 + rowbase + r)     * NKV + c0;
        float* rowp1 = attnF + ((size_t)bh * NMM + q0 + rowbase + r + 8) * NKV + c0;
        #pragma unroll
        for (int nt = 0; nt < 32; nt++) {
            float2 v0 = { c[nt][0], c[nt][1] };
            float2 v1 = { c[nt][2], c[nt][3] };
            *reinterpret_cast<float2*>(rowp0 + nt * 8) = v0;
            *reinterpret_cast<float2*>(rowp1 + nt * 8) = v1;
        }
    }

    cp_wait<0>();
    __syncthreads();

    float o[8][4];
    #pragma unroll
    for (int j = 0; j < 8; j++)
        #pragma unroll
        for (int k = 0; k < 4; k++) o[j][k] = 0.0f;

    #pragma unroll
    for (int kt = 0; kt < 16; kt++) {
        uint32_t a[4];
        a[0] = pack_h(c[2 * kt][0],     c[2 * kt][1]);
        a[1] = pack_h(c[2 * kt][2],     c[2 * kt][3]);
        a[2] = pack_h(c[2 * kt + 1][0], c[2 * kt + 1][1]);
        a[3] = pack_h(c[2 * kt + 1][2], c[2 * kt + 1][3]);
        #pragma unroll
        for (int dblk = 0; dblk < 4; dblk++) {
            uint32_t v0, v1, v2, v3;
            const uint32_t vb = sb + FA_V + (kt * 16 + lr) * FA_PAD + dblk * 32 + lc16;
            ldsm4t(v0, v1, v2, v3, vb);
            mma16816(o[dblk * 2],     a, v0, v1);
            mma16816(o[dblk * 2 + 1], a, v2, v3);
        }
    }

    const int b = bh / HEADS, h = bh % HEADS;
    const int r = lane >> 2;
    #pragma unroll
    for (int j = 0; j < 8; j++) {
        const int d = j * 8 + (lane & 3) * 2;
        #pragma unroll
        for (int s = 0; s < 2; s++) {
            const int q = q0 + rowbase + r + s * 8;
            size_t idx = ((size_t)(b * NMM + q)) * DIM + h * HD + d;
            *reinterpret_cast<uint32_t*>(Oh + idx) = pack_h(o[j][s * 2], o[j][s * 2 + 1]);
        }
    }
}

// ---------------------------------------------------------------------------
// Launch
// ---------------------------------------------------------------------------
extern "C" void kernel_launch(void* const* d_in, const int* in_sizes, int n_in,
                              void* d_out, int out_size) {
    const float* xmm   = (const float*)d_in[0];
    const float* xv    = (const float*)d_in[1];
    const float* xa    = (const float*)d_in[2];
    const float* Wq    = (const float*)d_in[3];
    const float* Wkv   = (const float*)d_in[4];
    const float* Wproj = (const float*)d_in[5];
    const float* bproj = (const float*)d_in[6];
    float* out = (float*)d_out;

    __half *xmm_h, *xmm_l, *xsrc_h;
    __half *WqT_h, *WkvT_h, *WpT_h;
    __half *Qh, *Ql, *Kh, *Vh, *Oh;
    float* attn_fb;
    cudaGetSymbolAddress((void**)&xmm_h,  g_xmm_h);
    cudaGetSymbolAddress((void**)&xmm_l,  g_xmm_l);
    cudaGetSymbolAddress((void**)&xsrc_h, g_xsrc_h);
    cudaGetSymbolAddress((void**)&WqT_h,  g_WqT_h);
    cudaGetSymbolAddress((void**)&WkvT_h, g_WkvT_h);
    cudaGetSymbolAddress((void**)&WpT_h,  g_WpT_h);
    cudaGetSymbolAddress((void**)&Qh,  g_Qh);
    cudaGetSymbolAddress((void**)&Ql,  g_Ql);
    cudaGetSymbolAddress((void**)&Kh,  g_Kh);
    cudaGetSymbolAddress((void**)&Vh,  g_Vh);
    cudaGetSymbolAddress((void**)&Oh,  g_Oh);
    cudaGetSymbolAddress((void**)&attn_fb, g_attn_fallback);

    const int writeAttn = (out_size >= (OUT_ELEMS + ATTN_ELEMS)) ? 1 : 0;
    float* attn = writeAttn ? (out + OUT_ELEMS) : attn_fb;

    cudaFuncSetAttribute(qkv_proj_kernel, cudaFuncAttributeMaxDynamicSharedMemorySize, QKV_SMEM);
    cudaFuncSetAttribute(out_proj_kernel, cudaFuncAttributeMaxDynamicSharedMemorySize, OPROJ_SMEM);
    cudaFuncSetAttribute(fused_attn_kernel, cudaFuncAttributeMaxDynamicSharedMemorySize, FA_SMEM);

    // 1) input splits + weight transposes, one launch
    prep_all_kernel<<<PREP_BLOCKS + TR_BLOCKS, 256>>>(
        (const float4*)xmm, xv, xa,
        (uint2*)xmm_h, (uint2*)xmm_l, (uint2*)xsrc_h,
        Wq, Wkv, Wproj, WqT_h, WkvT_h, WpT_h);

    // 2) merged Q (2-term) + KV (1-term) projections
    qkv_proj_kernel<<<dim3(18, M_ROWS / 128), 256, QKV_SMEM>>>(
        xmm_h, xmm_l, WqT_h, xsrc_h, WkvT_h, Qh, Ql, Kh, Vh);

    // 3) fused QK + softmax + attn write + AV
    fused_attn_kernel<<<dim3(NMM / 64, NBH), 128, FA_SMEM>>>(
        Qh, Ql, Kh, Vh, attn, Oh, writeAttn);

    // 4) lean out-proj (3 CTAs/SM, single wave)
    out_proj_kernel<<<dim3(6, M_ROWS / 128), 256, OPROJ_SMEM>>>(
        Oh, WpT_h, bproj, out);
}

// round 11
// speedup vs baseline: 1.6687x; 1.6687x over previous
#include <cuda_runtime.h>
#include <cuda_fp16.h>
#include <math.h>
#include <stdint.h>

#define BS    32
#define NMM   256
#define NV    196
#define NA    60
#define NKV   256
#define DIM   768
#define HEADS 12
#define HD    64
#define KVDIM 1536

#define OUT_ELEMS  (BS * NMM * DIM)
#define ATTN_ELEMS (BS * HEADS * NMM * NKV)
#define M_ROWS     (BS * NMM)
#define NBH        (BS * HEADS)

// ---------------------------------------------------------------------------
// Scratch
// ---------------------------------------------------------------------------
__device__ __half g_xmm_h[M_ROWS * DIM];
__device__ __half g_xmm_l[M_ROWS * DIM];
__device__ __half g_xsrc_h[M_ROWS * DIM];
__device__ __half g_WqT_h[DIM * DIM];
__device__ __half g_WkvT_h[KVDIM * DIM];
__device__ __half g_WpT_h[DIM * DIM];

__device__ __half g_Qh[NBH * NMM * HD];
__device__ __half g_Ql[NBH * NMM * HD];
__device__ __half g_Kh[NBH * NKV * HD];
__device__ __half g_Vh[NBH * NKV * HD];
__device__ __half g_Oh[M_ROWS * DIM];
__device__ float g_attn_fallback[ATTN_ELEMS];

// ---------------------------------------------------------------------------
// PTX helpers
// ---------------------------------------------------------------------------
__device__ __forceinline__ uint32_t smem_u32(const void* p) {
    uint32_t a;
    asm("{ .reg .u64 t; cvta.to.shared.u64 t, %1; cvt.u32.u64 %0, t; }" : "=r"(a) : "l"(p));
    return a;
}
__device__ __forceinline__ void cp_async16(uint32_t sa, const void* gp) {
    asm volatile("cp.async.cg.shared.global [%0], [%1], 16;" :: "r"(sa), "l"(gp) : "memory");
}
__device__ __forceinline__ void cp_commit() {
    asm volatile("cp.async.commit_group;" ::: "memory");
}
template <int N>
__device__ __forceinline__ void cp_wait() {
    asm volatile("cp.async.wait_group %0;" :: "n"(N) : "memory");
}
__device__ __forceinline__ void ldsm4(uint32_t& r0, uint32_t& r1, uint32_t& r2, uint32_t& r3,
                                      uint32_t addr) {
    asm volatile("ldmatrix.sync.aligned.m8n8.x4.shared.b16 {%0,%1,%2,%3}, [%4];"
                 : "=r"(r0), "=r"(r1), "=r"(r2), "=r"(r3) : "r"(addr));
}
__device__ __forceinline__ void ldsm4t(uint32_t& r0, uint32_t& r1, uint32_t& r2, uint32_t& r3,
                                       uint32_t addr) {
    asm volatile("ldmatrix.sync.aligned.m8n8.x4.trans.shared.b16 {%0,%1,%2,%3}, [%4];"
                 : "=r"(r0), "=r"(r1), "=r"(r2), "=r"(r3) : "r"(addr));
}
__device__ __forceinline__ void mma16816(float* c, const uint32_t* a, uint32_t b0, uint32_t b1) {
    asm volatile(
        "mma.sync.aligned.m16n8k16.row.col.f32.f16.f16.f32 "
        "{%0,%1,%2,%3}, {%4,%5,%6,%7}, {%8,%9}, {%0,%1,%2,%3};"
        : "+f"(c[0]), "+f"(c[1]), "+f"(c[2]), "+f"(c[3])
        : "r"(a[0]), "r"(a[1]), "r"(a[2]), "r"(a[3]), "r"(b0), "r"(b1));
}

__device__ __forceinline__ void pack_hl(float f0, float f1, uint32_t& h, uint32_t& l) {
    __half h0 = __float2half_rn(f0);
    __half h1 = __float2half_rn(f1);
    __half l0 = __float2half_rn(f0 - __half2float(h0));
    __half l1 = __float2half_rn(f1 - __half2float(h1));
    __half2 hp = __halves2half2(h0, h1);
    __half2 lp = __halves2half2(l0, l1);
    h = *reinterpret_cast<uint32_t*>(&hp);
    l = *reinterpret_cast<uint32_t*>(&lp);
}
__device__ __forceinline__ uint32_t pack_h(float f0, float f1) {
    __half2 hp = __halves2half2(__float2half_rn(f0), __float2half_rn(f1));
    return *reinterpret_cast<uint32_t*>(&hp);
}

// ---------------------------------------------------------------------------
// Fused input-prep + weight transposes (one launch, disjoint block ranges).
// ---------------------------------------------------------------------------
__device__ __forceinline__ void split4(float4 v, uint2& hv, uint2& lv) {
    uint32_t h0, l0, h1, l1;
    pack_hl(v.x, v.y, h0, l0);
    pack_hl(v.z, v.w, h1, l1);
    hv.x = h0; hv.y = h1; lv.x = l0; lv.y = l1;
}
__device__ __forceinline__ uint2 round4(float4 v) {
    uint2 hv;
    hv.x = pack_h(v.x, v.y);
    hv.y = pack_h(v.z, v.w);
    return hv;
}

#define N4 (M_ROWS * DIM / 4)
#define PREP_BLOCKS (2 * N4 / 256)
#define TR_BLOCKS   (96 * 24)

__global__ __launch_bounds__(256)
void prep_all_kernel(const float4* __restrict__ xmm,
                     const float* __restrict__ xv, const float* __restrict__ xa,
                     uint2* __restrict__ xmm_h, uint2* __restrict__ xmm_l,
                     uint2* __restrict__ xsrc_h,
                     const float* __restrict__ Wq, const float* __restrict__ Wkv,
                     const float* __restrict__ Wp,
                     __half* __restrict__ WqT, __half* __restrict__ WkvT,
                     __half* __restrict__ WpT) {
    const int bx = blockIdx.x;
    if (bx < PREP_BLOCKS) {
        int i = bx * 256 + threadIdx.x;
        if (i < N4) {
            uint2 hv, lv;
            split4(xmm[i], hv, lv);
            xmm_h[i] = hv;
            xmm_l[i] = lv;
        } else {
            i -= N4;
            const int C4 = DIM / 4;
            int row = i / C4;
            int c4  = i - row * C4;
            int b = row >> 8;
            int r = row & 255;
            const float4* src = (r < NV)
                ? reinterpret_cast<const float4*>(xv + (size_t)(b * NV + r) * DIM)
                : reinterpret_cast<const float4*>(xa + (size_t)(b * NA + (r - NV)) * DIM);
            xsrc_h[i] = round4(src[c4]);
        }
    } else {
        __shared__ float t[32][33];
        int b2 = bx - PREP_BLOCKS;
        int nbx = b2 % 96;
        int ky  = b2 / 96;
        const float* W; __half* T; int N; int nb;
        if (nbx < 24)      { W = Wq;  T = WqT;  N = DIM;   nb = nbx; }
        else if (nbx < 72) { W = Wkv; T = WkvT; N = KVDIM; nb = nbx - 24; }
        else               { W = Wp;  T = WpT;  N = DIM;   nb = nbx - 72; }
        int k0 = ky * 32, n0 = nb * 32;
        int x = threadIdx.x & 31, y = threadIdx.x >> 5;
        #pragma unroll
        for (int i = 0; i < 32; i += 8)
            t[y + i][x] = W[(size_t)(k0 + y + i) * N + n0 + x];
        __syncthreads();
        #pragma unroll
        for (int i = 0; i < 32; i += 8)
            T[(size_t)(n0 + y + i) * DIM + k0 + x] = __float2half_rn(t[x][y + i]);
    }
}

// ---------------------------------------------------------------------------
// Shared GEMM mainloop, TWOTERM is COMPILE-TIME (no runtime branches in the
// unrolled body). Tile 128x128, BK=32, 3-stage cp.async. Stage layout always
// reserves 3 arrays (Ah, Al, B) so resources match round 9 exactly.
// ---------------------------------------------------------------------------
#define GK 768
#define PAD_ROW 80
#define ARR_BYTES (128 * PAD_ROW)
#define STAGE_BYTES (3 * ARR_BYTES)
#define GEMM_SMEM (3 * STAGE_BYTES)     // 92160

template <bool TWOTERM>
__device__ __forceinline__ void gemm_mainloop(
    float (&c)[4][4][4],
    const __half* __restrict__ base0, const __half* __restrict__ base1,
    const __half* __restrict__ base2,
    uint32_t sb, int tid, int lane, int wid)
{
    const int wr   = wid >> 2;
    const int wc   = wid & 3;
    const int lr   = lane & 15;
    const int lc16 = (lane >> 4) * 16;

    auto issue_stage = [&](int chunk, int s) {
        const int k0 = chunk << 5;
        const uint32_t sbase = sb + s * STAGE_BYTES;
        #pragma unroll
        for (int it = 0; it < 6; it++) {
            const int arr = it >> 1;
            if (arr == 1 && !TWOTERM) continue;    // compile-time
            const int j   = tid + (it & 1) * 256;
            const int row = j >> 2;
            const int q   = j & 3;
            const __half* gp =
                (arr == 0 ? base0 : arr == 1 ? base1 : base2)
                + (size_t)row * GK + k0 + q * 8;
            cp_async16(sbase + arr * ARR_BYTES + row * PAD_ROW + q * 16, gp);
        }
        cp_commit();
    };

    #pragma unroll
    for (int i = 0; i < 4; i++)
        #pragma unroll
        for (int j = 0; j < 4; j++)
            #pragma unroll
            for (int k = 0; k < 4; k++) c[i][j][k] = 0.0f;

    issue_stage(0, 0);
    issue_stage(1, 1);

    const int nchunks = GK / 32;  // 24
    for (int i = 0; i < nchunks; i++) {
        if (i + 1 < nchunks) cp_wait<1>(); else cp_wait<0>();
        __syncthreads();
        if (i + 2 < nchunks) issue_stage(i + 2, (i + 2) % 3);

        const uint32_t st = sb + (i % 3) * STAGE_BYTES;
        const uint32_t aH_base = st + 0 * ARR_BYTES + (wr * 64 + lr) * PAD_ROW + lc16;
        const uint32_t aL_base = st + 1 * ARR_BYTES + (wr * 64 + lr) * PAD_ROW + lc16;
        const uint32_t bH_base = st + 2 * ARR_BYTES + (wc * 32 + lr) * PAD_ROW + lc16;

        #pragma unroll
        for (int kk = 0; kk < 2; kk++) {
            const uint32_t ko = kk * 32;
            uint32_t bh[4][2];
            #pragma unroll
            for (int bt = 0; bt < 2; bt++) {
                uint32_t r0, r1, r2, r3;
                ldsm4(r0, r1, r2, r3, bH_base + bt * 16 * PAD_ROW + ko);
                bh[bt * 2 + 0][0] = r0; bh[bt * 2 + 0][1] = r2;
                bh[bt * 2 + 1][0] = r1; bh[bt * 2 + 1][1] = r3;
            }
            #pragma unroll
            for (int mt = 0; mt < 4; mt++) {
                uint32_t aH[4];
                ldsm4(aH[0], aH[1], aH[2], aH[3], aH_base + mt * 16 * PAD_ROW + ko);
                #pragma unroll
                for (int ni = 0; ni < 4; ni++) mma16816(c[mt][ni], aH, bh[ni][0], bh[ni][1]);
                if (TWOTERM) {
                    uint32_t aL[4];
                    ldsm4(aL[0], aL[1], aL[2], aL[3], aL_base + mt * 16 * PAD_ROW + ko);
                    #pragma unroll
                    for (int ni = 0; ni < 4; ni++) mma16816(c[mt][ni], aL, bh[ni][0], bh[ni][1]);
                }
            }
        }
    }
}

// ---------------------------------------------------------------------------
// Merged Q + KV projection. blockIdx.x < 6: Q (2-term, hi/lo split epi).
// blockIdx.x >= 6: KV (1-term, K/V hi epi). One uniform top-level branch.
// ---------------------------------------------------------------------------
__global__ __launch_bounds__(256, 2)
void qkv_proj_kernel(const __half* __restrict__ Amh, const __half* __restrict__ Aml,
                     const __half* __restrict__ QT,
                     const __half* __restrict__ Ash, const __half* __restrict__ KVT,
                     __half* __restrict__ QhO, __half* __restrict__ QlO,
                     __half* __restrict__ KhO, __half* __restrict__ VhO) {
    extern __shared__ char smem[];
    const uint32_t sb = smem_u32(smem);
    const int tid  = threadIdx.x;
    const int lane = tid & 31;
    const int wid  = tid >> 5;
    const int wr   = wid >> 2;
    const int wc   = wid & 3;
    const int m0   = blockIdx.y * 128;

    float c[4][4][4];

    if (blockIdx.x < 6) {
        const int n0 = blockIdx.x * 128;
        gemm_mainloop<true>(c, Amh + (size_t)m0 * GK, Aml + (size_t)m0 * GK,
                            QT + (size_t)n0 * GK, sb, tid, lane, wid);
        const int crow0 = m0 + wr * 64 + (lane >> 2);
        const int ccol0 = n0 + wc * 32 + (lane & 3) * 2;
        #pragma unroll
        for (int mt = 0; mt < 4; mt++) {
            #pragma unroll
            for (int ni = 0; ni < 4; ni++) {
                const int cc = ccol0 + ni * 8;
                const float* cf = c[mt][ni];
                const int h = cc >> 6, d = cc & 63;
                #pragma unroll
                for (int s = 0; s < 2; s++) {
                    const int r = crow0 + mt * 16 + s * 8;
                    const int b = r >> 8, q = r & 255;
                    size_t idx = (((size_t)(b * HEADS + h)) * NMM + q) * HD + d;
                    uint32_t hh, ll;
                    pack_hl(cf[s * 2], cf[s * 2 + 1], hh, ll);
                    *reinterpret_cast<uint32_t*>(QhO + idx) = hh;
                    *reinterpret_cast<uint32_t*>(QlO + idx) = ll;
                }
            }
        }
    } else {
        const int n0 = (blockIdx.x - 6) * 128;
        gemm_mainloop<false>(c, Ash + (size_t)m0 * GK, nullptr,
                             KVT + (size_t)n0 * GK, sb, tid, lane, wid);
        const int crow0 = m0 + wr * 64 + (lane >> 2);
        const int ccol0 = n0 + wc * 32 + (lane & 3) * 2;
        #pragma unroll
        for (int mt = 0; mt < 4; mt++) {
            #pragma unroll
            for (int ni = 0; ni < 4; ni++) {
                const int cc = ccol0 + ni * 8;
                const float* cf = c[mt][ni];
                const bool isK = (cc < DIM);
                const int ccl = isK ? cc : cc - DIM;
                const int h = ccl >> 6, d = ccl & 63;
                __half* Hd = isK ? KhO : VhO;
                #pragma unroll
                for (int s = 0; s < 2; s++) {
                    const int r = crow0 + mt * 16 + s * 8;
                    const int b = r >> 8, t = r & 255;
                    size_t idx = (((size_t)(b * HEADS + h)) * NKV + t) * HD + d;
                    *reinterpret_cast<uint32_t*>(Hd + idx) = pack_h(cf[s * 2], cf[s * 2 + 1]);
                }
            }
        }
    }
}

// ---------------------------------------------------------------------------
// Out-projection (round-9 resources: 2 CTAs/SM, no reg cap stress).
// ---------------------------------------------------------------------------
__global__ __launch_bounds__(256, 2)
void out_proj_kernel(const __half* __restrict__ Ah, const __half* __restrict__ BT,
                     const float* __restrict__ bias, float* __restrict__ C) {
    extern __shared__ char smem[];
    const uint32_t sb = smem_u32(smem);
    const int tid  = threadIdx.x;
    const int lane = tid & 31;
    const int wid  = tid >> 5;
    const int wr   = wid >> 2;
    const int wc   = wid & 3;
    const int m0   = blockIdx.y * 128;
    const int n0   = blockIdx.x * 128;

    float c[4][4][4];
    gemm_mainloop<false>(c, Ah + (size_t)m0 * GK, nullptr,
                         BT + (size_t)n0 * GK, sb, tid, lane, wid);

    const int crow0 = m0 + wr * 64 + (lane >> 2);
    const int ccol0 = n0 + wc * 32 + (lane & 3) * 2;
    #pragma unroll
    for (int mt = 0; mt < 4; mt++) {
        #pragma unroll
        for (int ni = 0; ni < 4; ni++) {
            const int cc = ccol0 + ni * 8;
            const float* cf = c[mt][ni];
            const int r0 = crow0 + mt * 16;
            float b0 = bias[cc], b1 = bias[cc + 1];
            float2 v0 = { cf[0] + b0, cf[1] + b1 };
            float2 v1 = { cf[2] + b0, cf[3] + b1 };
            *reinterpret_cast<float2*>(C + (size_t)r0 * DIM + cc) = v0;
            *reinterpret_cast<float2*>(C + (size_t)(r0 + 8) * DIM + cc) = v1;
        }
    }
}

// ---------------------------------------------------------------------------
// Fused attention (unchanged from round 9): QK + softmax + attn write + AV.
// ---------------------------------------------------------------------------
#define FA_PAD 144
#define FA_QH 0
#define FA_QL (64 * FA_PAD)
#define FA_K  (2 * 64 * FA_PAD)
#define FA_V  (FA_K + 256 * FA_PAD)
#define FA_SMEM (FA_V + 256 * FA_PAD)     // 92160

__global__ __launch_bounds__(128, 2)
void fused_attn_kernel(const __half* __restrict__ Qh, const __half* __restrict__ Ql,
                       const __half* __restrict__ Kh, const __half* __restrict__ Vh,
                       float* __restrict__ attnF, __half* __restrict__ Oh,
                       int writeAttn) {
    extern __shared__ char smem[];
    const uint32_t sb = smem_u32(smem);
    const int bh = blockIdx.y;
    const int q0 = blockIdx.x * 64;
    const int tid  = threadIdx.x;
    const int lane = tid & 31;
    const int wid  = tid >> 5;

    const __half* gQh = Qh + ((size_t)bh * NMM + q0) * HD;
    const __half* gQl = Ql + ((size_t)bh * NMM + q0) * HD;
    const __half* gKh = Kh + (size_t)bh * NKV * HD;
    const __half* gVh = Vh + (size_t)bh * NKV * HD;

    for (int idx = tid; idx < 512; idx += 128) {
        int row = idx >> 3, cq = idx & 7;
        cp_async16(sb + FA_QH + row * FA_PAD + cq * 16, gQh + row * HD + cq * 8);
        cp_async16(sb + FA_QL + row * FA_PAD + cq * 16, gQl + row * HD + cq * 8);
    }
    for (int idx = tid; idx < 2048; idx += 128) {
        int row = idx >> 3, cq = idx & 7;
        cp_async16(sb + FA_K + row * FA_PAD + cq * 16, gKh + row * HD + cq * 8);
    }
    cp_commit();
    for (int idx = tid; idx < 2048; idx += 128) {
        int row = idx >> 3, cq = idx & 7;
        cp_async16(sb + FA_V + row * FA_PAD + cq * 16, gVh + row * HD + cq * 8);
    }
    cp_commit();

    cp_wait<1>();
    __syncthreads();

    const int lr = lane & 15;
    const int lc16 = (lane >> 4) * 16;
    const int rowbase = wid * 16;

    float c[32][4];
    #pragma unroll
    for (int j = 0; j < 32; j++)
        #pragma unroll
        for (int k = 0; k < 4; k++) c[j][k] = 0.0f;

    #pragma unroll
    for (int kk = 0; kk < 4; kk++) {
        const uint32_t ko = kk * 32;
        uint32_t aH[4], aL[4];
        const uint32_t ab = sb + FA_QH + (rowbase + lr) * FA_PAD + ko + lc16;
        ldsm4(aH[0], aH[1], aH[2], aH[3], ab);
        ldsm4(aL[0], aL[1], aL[2], aL[3], ab + FA_QL);
        #pragma unroll
        for (int tb = 0; tb < 16; tb++) {
            const uint32_t bb = sb + FA_K + (tb * 16 + lr) * FA_PAD + ko + lc16;
            uint32_t h0, h1, h2, h3;
            ldsm4(h0, h1, h2, h3, bb);
            mma16816(c[tb * 2],     aH, h0, h2);
            mma16816(c[tb * 2],     aL, h0, h2);
            mma16816(c[tb * 2 + 1], aH, h1, h3);
            mma16816(c[tb * 2 + 1], aL, h1, h3);
        }
    }

    const float scale = 0.125f;
    #pragma unroll
    for (int s2 = 0; s2 < 2; s2++) {
        float m = -INFINITY;
        #pragma unroll
        for (int nt = 0; nt < 32; nt++) {
            m = fmaxf(m, c[nt][s2 * 2]);
            m = fmaxf(m, c[nt][s2 * 2 + 1]);
        }
        m = fmaxf(m, __shfl_xor_sync(0xffffffffu, m, 1));
        m = fmaxf(m, __shfl_xor_sync(0xffffffffu, m, 2));
        float sum = 0.0f;
        #pragma unroll
        for (int nt = 0; nt < 32; nt++) {
            float e0 = __expf((c[nt][s2 * 2]     - m) * scale);
            float e1 = __expf((c[nt][s2 * 2 + 1] - m) * scale);
            c[nt][s2 * 2]     = e0;
            c[nt][s2 * 2 + 1] = e1;
            sum += e0 + e1;
        }
        sum += __shfl_xor_sync(0xffffffffu, sum, 1);
        sum += __shfl_xor_sync(0xffffffffu, sum, 2);
        float inv = 1.0f / sum;
        #pragma unroll
        for (int nt = 0; nt < 32; nt++) {
            c[nt][s2 * 2]     *= inv;
            c[nt][s2 * 2 + 1] *= inv;
        }
    }

    if (writeAttn) {
        const int r  = lane >> 2;
        const int c0 = (lane & 3) * 2;
        float* rowp0 = attnF + ((size_t)bh * NMM + q0 + rowbase + r)     * NKV + c0;
        float* rowp1 = attnF + ((size_t)bh * NMM + q0 + rowbase + r + 8) * NKV + c0;
        #pragma unroll
        for (int nt = 0; nt < 32; nt++) {
            float2 v0 = { c[nt][0], c[nt][1] };
            float2 v1 = { c[nt][2], c[nt][3] };
            *reinterpret_cast<float2*>(rowp0 + nt * 8) = v0;
            *reinterpret_cast<float2*>(rowp1 + nt * 8) = v1;
        }
    }

    cp_wait<0>();
    __syncthreads();

    float o[8][4];
    #pragma unroll
    for (int j = 0; j < 8; j++)
        #pragma unroll
        for (int k = 0; k < 4; k++) o[j][k] = 0.0f;

    #pragma unroll
    for (int kt = 0; kt < 16; kt++) {
        uint32_t a[4];
        a[0] = pack_h(c[2 * kt][0],     c[2 * kt][1]);
        a[1] = pack_h(c[2 * kt][2],     c[2 * kt][3]);
        a[2] = pack_h(c[2 * kt + 1][0], c[2 * kt + 1][1]);
        a[3] = pack_h(c[2 * kt + 1][2], c[2 * kt + 1][3]);
        #pragma unroll
        for (int dblk = 0; dblk < 4; dblk++) {
            uint32_t v0, v1, v2, v3;
            const uint32_t vb = sb + FA_V + (kt * 16 + lr) * FA_PAD + dblk * 32 + lc16;
            ldsm4t(v0, v1, v2, v3, vb);
            mma16816(o[dblk * 2],     a, v0, v1);
            mma16816(o[dblk * 2 + 1], a, v2, v3);
        }
    }

    const int b = bh / HEADS, h = bh % HEADS;
    const int r = lane >> 2;
    #pragma unroll
    for (int j = 0; j < 8; j++) {
        const int d = j * 8 + (lane & 3) * 2;
        #pragma unroll
        for (int s = 0; s < 2; s++) {
            const int q = q0 + rowbase + r + s * 8;
            size_t idx = ((size_t)(b * NMM + q)) * DIM + h * HD + d;
            *reinterpret_cast<uint32_t*>(Oh + idx) = pack_h(o[j][s * 2], o[j][s * 2 + 1]);
        }
    }
}

// ---------------------------------------------------------------------------
// Launch
// ---------------------------------------------------------------------------
extern "C" void kernel_launch(void* const* d_in, const int* in_sizes, int n_in,
                              void* d_out, int out_size) {
    const float* xmm   = (const float*)d_in[0];
    const float* xv    = (const float*)d_in[1];
    const float* xa    = (const float*)d_in[2];
    const float* Wq    = (const float*)d_in[3];
    const float* Wkv   = (const float*)d_in[4];
    const float* Wproj = (const float*)d_in[5];
    const float* bproj = (const float*)d_in[6];
    float* out = (float*)d_out;

    __half *xmm_h, *xmm_l, *xsrc_h;
    __half *WqT_h, *WkvT_h, *WpT_h;
    __half *Qh, *Ql, *Kh, *Vh, *Oh;
    float* attn_fb;
    cudaGetSymbolAddress((void**)&xmm_h,  g_xmm_h);
    cudaGetSymbolAddress((void**)&xmm_l,  g_xmm_l);
    cudaGetSymbolAddress((void**)&xsrc_h, g_xsrc_h);
    cudaGetSymbolAddress((void**)&WqT_h,  g_WqT_h);
    cudaGetSymbolAddress((void**)&WkvT_h, g_WkvT_h);
    cudaGetSymbolAddress((void**)&WpT_h,  g_WpT_h);
    cudaGetSymbolAddress((void**)&Qh,  g_Qh);
    cudaGetSymbolAddress((void**)&Ql,  g_Ql);
    cudaGetSymbolAddress((void**)&Kh,  g_Kh);
    cudaGetSymbolAddress((void**)&Vh,  g_Vh);
    cudaGetSymbolAddress((void**)&Oh,  g_Oh);
    cudaGetSymbolAddress((void**)&attn_fb, g_attn_fallback);

    const int writeAttn = (out_size >= (OUT_ELEMS + ATTN_ELEMS)) ? 1 : 0;
    float* attn = writeAttn ? (out + OUT_ELEMS) : attn_fb;

    cudaFuncSetAttribute(qkv_proj_kernel, cudaFuncAttributeMaxDynamicSharedMemorySize, GEMM_SMEM);
    cudaFuncSetAttribute(out_proj_kernel, cudaFuncAttributeMaxDynamicSharedMemorySize, GEMM_SMEM);
    cudaFuncSetAttribute(fused_attn_kernel, cudaFuncAttributeMaxDynamicSharedMemorySize, FA_SMEM);

    // 1) input splits + weight transposes, one launch
    prep_all_kernel<<<PREP_BLOCKS + TR_BLOCKS, 256>>>(
        (const float4*)xmm, xv, xa,
        (uint2*)xmm_h, (uint2*)xmm_l, (uint2*)xsrc_h,
        Wq, Wkv, Wproj, WqT_h, WkvT_h, WpT_h);

    // 2) merged Q (2-term) + KV (1-term) projections, branch-free bodies
    qkv_proj_kernel<<<dim3(18, M_ROWS / 128), 256, GEMM_SMEM>>>(
        xmm_h, xmm_l, WqT_h, xsrc_h, WkvT_h, Qh, Ql, Kh, Vh);

    // 3) fused QK + softmax + attn write + AV
    fused_attn_kernel<<<dim3(NMM / 64, NBH), 128, FA_SMEM>>>(
        Qh, Ql, Kh, Vh, attn, Oh, writeAttn);

    // 4) out-proj (round-9 resources)
    out_proj_kernel<<<dim3(6, M_ROWS / 128), 256, GEMM_SMEM>>>(
        Oh, WpT_h, bproj, out);
}

// round 14
// speedup vs baseline: 2.1297x; 1.2763x over previous
#include <cuda_runtime.h>
#include <cuda_fp16.h>
#include <math.h>
#include <stdint.h>

#define BS    32
#define NMM   256
#define NV    196
#define NA    60
#define NKV   256
#define DIM   768
#define HEADS 12
#define HD    64
#define KVDIM 1536

#define OUT_ELEMS  (BS * NMM * DIM)
#define ATTN_ELEMS (BS * HEADS * NMM * NKV)
#define M_ROWS     (BS * NMM)
#define NBH        (BS * HEADS)

// ---------------------------------------------------------------------------
// Scratch (all fp16 hi-only now)
// ---------------------------------------------------------------------------
__device__ __half g_xmm_h[M_ROWS * DIM];
__device__ __half g_xsrc_h[M_ROWS * DIM];
__device__ __half g_WqT_h[DIM * DIM];
__device__ __half g_WkvT_h[KVDIM * DIM];
__device__ __half g_WpT_h[DIM * DIM];

__device__ __half g_Qh[NBH * NMM * HD];
__device__ __half g_Kh[NBH * NKV * HD];
__device__ __half g_Vh[NBH * NKV * HD];
__device__ __half g_Oh[M_ROWS * DIM];
__device__ float g_attn_fallback[ATTN_ELEMS];

// ---------------------------------------------------------------------------
// PTX helpers
// ---------------------------------------------------------------------------
__device__ __forceinline__ uint32_t smem_u32(const void* p) {
    uint32_t a;
    asm("{ .reg .u64 t; cvta.to.shared.u64 t, %1; cvt.u32.u64 %0, t; }" : "=r"(a) : "l"(p));
    return a;
}
__device__ __forceinline__ void cp_async16(uint32_t sa, const void* gp) {
    asm volatile("cp.async.cg.shared.global [%0], [%1], 16;" :: "r"(sa), "l"(gp) : "memory");
}
__device__ __forceinline__ void cp_commit() {
    asm volatile("cp.async.commit_group;" ::: "memory");
}
template <int N>
__device__ __forceinline__ void cp_wait() {
    asm volatile("cp.async.wait_group %0;" :: "n"(N) : "memory");
}
__device__ __forceinline__ void ldsm4(uint32_t& r0, uint32_t& r1, uint32_t& r2, uint32_t& r3,
                                      uint32_t addr) {
    asm volatile("ldmatrix.sync.aligned.m8n8.x4.shared.b16 {%0,%1,%2,%3}, [%4];"
                 : "=r"(r0), "=r"(r1), "=r"(r2), "=r"(r3) : "r"(addr));
}
__device__ __forceinline__ void ldsm4t(uint32_t& r0, uint32_t& r1, uint32_t& r2, uint32_t& r3,
                                       uint32_t addr) {
    asm volatile("ldmatrix.sync.aligned.m8n8.x4.trans.shared.b16 {%0,%1,%2,%3}, [%4];"
                 : "=r"(r0), "=r"(r1), "=r"(r2), "=r"(r3) : "r"(addr));
}
__device__ __forceinline__ void mma16816(float* c, const uint32_t* a, uint32_t b0, uint32_t b1) {
    asm volatile(
        "mma.sync.aligned.m16n8k16.row.col.f32.f16.f16.f32 "
        "{%0,%1,%2,%3}, {%4,%5,%6,%7}, {%8,%9}, {%0,%1,%2,%3};"
        : "+f"(c[0]), "+f"(c[1]), "+f"(c[2]), "+f"(c[3])
        : "r"(a[0]), "r"(a[1]), "r"(a[2]), "r"(a[3]), "r"(b0), "r"(b1));
}

__device__ __forceinline__ uint32_t pack_h(float f0, float f1) {
    __half2 hp = __halves2half2(__float2half_rn(f0), __float2half_rn(f1));
    return *reinterpret_cast<uint32_t*>(&hp);
}
__device__ __forceinline__ uint2 round4(float4 v) {
    uint2 hv;
    hv.x = pack_h(v.x, v.y);
    hv.y = pack_h(v.z, v.w);
    return hv;
}

// ---------------------------------------------------------------------------
// Fused input-prep + weight transposes (one launch, disjoint block ranges).
// ---------------------------------------------------------------------------
#define N4 (M_ROWS * DIM / 4)
#define PREP_BLOCKS (2 * N4 / 256)
#define TR_BLOCKS   (96 * 24)

__global__ __launch_bounds__(256)
void prep_all_kernel(const float4* __restrict__ xmm,
                     const float* __restrict__ xv, const float* __restrict__ xa,
                     uint2* __restrict__ xmm_h, uint2* __restrict__ xsrc_h,
                     const float* __restrict__ Wq, const float* __restrict__ Wkv,
                     const float* __restrict__ Wp,
                     __half* __restrict__ WqT, __half* __restrict__ WkvT,
                     __half* __restrict__ WpT) {
    const int bx = blockIdx.x;
    if (bx < PREP_BLOCKS) {
        int i = bx * 256 + threadIdx.x;
        if (i < N4) {
            xmm_h[i] = round4(xmm[i]);
        } else {
            i -= N4;
            const int C4 = DIM / 4;
            int row = i / C4;
            int c4  = i - row * C4;
            int b = row >> 8;
            int r = row & 255;
            const float4* src = (r < NV)
                ? reinterpret_cast<const float4*>(xv + (size_t)(b * NV + r) * DIM)
                : reinterpret_cast<const float4*>(xa + (size_t)(b * NA + (r - NV)) * DIM);
            xsrc_h[i] = round4(src[c4]);
        }
    } else {
        __shared__ float t[32][33];
        int b2 = bx - PREP_BLOCKS;
        int nbx = b2 % 96;
        int ky  = b2 / 96;
        const float* W; __half* T; int N; int nb;
        if (nbx < 24)      { W = Wq;  T = WqT;  N = DIM;   nb = nbx; }
        else if (nbx < 72) { W = Wkv; T = WkvT; N = KVDIM; nb = nbx - 24; }
        else               { W = Wp;  T = WpT;  N = DIM;   nb = nbx - 72; }
        int k0 = ky * 32, n0 = nb * 32;
        int x = threadIdx.x & 31, y = threadIdx.x >> 5;
        #pragma unroll
        for (int i = 0; i < 32; i += 8)
            t[y + i][x] = W[(size_t)(k0 + y + i) * N + n0 + x];
        __syncthreads();
        #pragma unroll
        for (int i = 0; i < 32; i += 8)
            T[(size_t)(n0 + y + i) * DIM + k0 + x] = __float2half_rn(t[x][y + i]);
    }
}

// ---------------------------------------------------------------------------
// Shared 1-term GEMM mainloop. Tile 128x128, BK=32, 3-stage cp.async,
// 2 smem arrays per stage (A, B) -> 61 KB total.
// ---------------------------------------------------------------------------
#define GK 768
#define PAD_ROW 80
#define ARR_BYTES (128 * PAD_ROW)
#define STAGE_BYTES (2 * ARR_BYTES)     // 20480
#define GEMM_SMEM (3 * STAGE_BYTES)     // 61440

__device__ __forceinline__ void gemm_mainloop1(
    float (&c)[4][4][4],
    const __half* __restrict__ baseA, const __half* __restrict__ baseB,
    uint32_t sb, int tid, int lane, int wid)
{
    const int wr   = wid >> 2;
    const int wc   = wid & 3;
    const int lr   = lane & 15;
    const int lc16 = (lane >> 4) * 16;

    auto issue_stage = [&](int chunk, int s) {
        const int k0 = chunk << 5;
        const uint32_t sbase = sb + s * STAGE_BYTES;
        #pragma unroll
        for (int it = 0; it < 4; it++) {
            const int arr = it >> 1;
            const int j   = tid + (it & 1) * 256;
            const int row = j >> 2;
            const int q   = j & 3;
            const __half* gp = (arr == 0 ? baseA : baseB) + (size_t)row * GK + k0 + q * 8;
            cp_async16(sbase + arr * ARR_BYTES + row * PAD_ROW + q * 16, gp);
        }
        cp_commit();
    };

    #pragma unroll
    for (int i = 0; i < 4; i++)
        #pragma unroll
        for (int j = 0; j < 4; j++)
            #pragma unroll
            for (int k = 0; k < 4; k++) c[i][j][k] = 0.0f;

    issue_stage(0, 0);
    issue_stage(1, 1);

    const int nchunks = GK / 32;  // 24
    for (int i = 0; i < nchunks; i++) {
        if (i + 1 < nchunks) cp_wait<1>(); else cp_wait<0>();
        __syncthreads();
        if (i + 2 < nchunks) issue_stage(i + 2, (i + 2) % 3);

        const uint32_t st = sb + (i % 3) * STAGE_BYTES;
        const uint32_t aH_base = st + 0 * ARR_BYTES + (wr * 64 + lr) * PAD_ROW + lc16;
        const uint32_t bH_base = st + 1 * ARR_BYTES + (wc * 32 + lr) * PAD_ROW + lc16;

        #pragma unroll
        for (int kk = 0; kk < 2; kk++) {
            const uint32_t ko = kk * 32;
            uint32_t bh[4][2];
            #pragma unroll
            for (int bt = 0; bt < 2; bt++) {
                uint32_t r0, r1, r2, r3;
                ldsm4(r0, r1, r2, r3, bH_base + bt * 16 * PAD_ROW + ko);
                bh[bt * 2 + 0][0] = r0; bh[bt * 2 + 0][1] = r2;
                bh[bt * 2 + 1][0] = r1; bh[bt * 2 + 1][1] = r3;
            }
            #pragma unroll
            for (int mt = 0; mt < 4; mt++) {
                uint32_t aH[4];
                ldsm4(aH[0], aH[1], aH[2], aH[3], aH_base + mt * 16 * PAD_ROW + ko);
                #pragma unroll
                for (int ni = 0; ni < 4; ni++) mma16816(c[mt][ni], aH, bh[ni][0], bh[ni][1]);
            }
        }
    }
}

// ---------------------------------------------------------------------------
// Merged Q + KV projection (all 1-term). Uniform mainloop; epilogue-only branch.
// blockIdx.x < 6: Q -> Qh [b,h,q,d]. Else: KV -> Kh / Vh [b,h,t,d].
// ---------------------------------------------------------------------------
__global__ __launch_bounds__(256, 2)
void qkv_proj_kernel(const __half* __restrict__ Amh, const __half* __restrict__ QT,
                     const __half* __restrict__ Ash, const __half* __restrict__ KVT,
                     __half* __restrict__ QhO, __half* __restrict__ KhO,
                     __half* __restrict__ VhO) {
    extern __shared__ char smem[];
    const uint32_t sb = smem_u32(smem);
    const int tid  = threadIdx.x;
    const int lane = tid & 31;
    const int wid  = tid >> 5;
    const int wr   = wid >> 2;
    const int wc   = wid & 3;
    const int m0   = blockIdx.y * 128;
    const bool isQ = (blockIdx.x < 6);
    const int n0   = isQ ? blockIdx.x * 128 : (blockIdx.x - 6) * 128;

    const __half* baseA = (isQ ? Amh : Ash) + (size_t)m0 * GK;
    const __half* baseB = (isQ ? QT : KVT) + (size_t)n0 * GK;

    float c[4][4][4];
    gemm_mainloop1(c, baseA, baseB, sb, tid, lane, wid);

    const int crow0 = m0 + wr * 64 + (lane >> 2);
    const int ccol0 = n0 + wc * 32 + (lane & 3) * 2;
    if (isQ) {
        #pragma unroll
        for (int mt = 0; mt < 4; mt++) {
            #pragma unroll
            for (int ni = 0; ni < 4; ni++) {
                const int cc = ccol0 + ni * 8;
                const float* cf = c[mt][ni];
                const int h = cc >> 6, d = cc & 63;
                #pragma unroll
                for (int s = 0; s < 2; s++) {
                    const int r = crow0 + mt * 16 + s * 8;
                    const int b = r >> 8, q = r & 255;
                    size_t idx = (((size_t)(b * HEADS + h)) * NMM + q) * HD + d;
                    *reinterpret_cast<uint32_t*>(QhO + idx) = pack_h(cf[s * 2], cf[s * 2 + 1]);
                }
            }
        }
    } else {
        #pragma unroll
        for (int mt = 0; mt < 4; mt++) {
            #pragma unroll
            for (int ni = 0; ni < 4; ni++) {
                const int cc = ccol0 + ni * 8;
                const float* cf = c[mt][ni];
                const bool isK = (cc < DIM);
                const int ccl = isK ? cc : cc - DIM;
                const int h = ccl >> 6, d = ccl & 63;
                __half* Hd = isK ? KhO : VhO;
                #pragma unroll
                for (int s = 0; s < 2; s++) {
                    const int r = crow0 + mt * 16 + s * 8;
                    const int b = r >> 8, t = r & 255;
                    size_t idx = (((size_t)(b * HEADS + h)) * NKV + t) * HD + d;
                    *reinterpret_cast<uint32_t*>(Hd + idx) = pack_h(cf[s * 2], cf[s * 2 + 1]);
                }
            }
        }
    }
}

// ---------------------------------------------------------------------------
// Out-projection (1-term), same mainloop.
// ---------------------------------------------------------------------------
__global__ __launch_bounds__(256, 2)
void out_proj_kernel(const __half* __restrict__ Ah, const __half* __restrict__ BT,
                     const float* __restrict__ bias, float* __restrict__ C) {
    extern __shared__ char smem[];
    const uint32_t sb = smem_u32(smem);
    const int tid  = threadIdx.x;
    const int lane = tid & 31;
    const int wid  = tid >> 5;
    const int wr   = wid >> 2;
    const int wc   = wid & 3;
    const int m0   = blockIdx.y * 128;
    const int n0   = blockIdx.x * 128;

    float c[4][4][4];
    gemm_mainloop1(c, Ah + (size_t)m0 * GK, BT + (size_t)n0 * GK, sb, tid, lane, wid);

    const int crow0 = m0 + wr * 64 + (lane >> 2);
    const int ccol0 = n0 + wc * 32 + (lane & 3) * 2;
    #pragma unroll
    for (int mt = 0; mt < 4; mt++) {
        #pragma unroll
        for (int ni = 0; ni < 4; ni++) {
            const int cc = ccol0 + ni * 8;
            const float* cf = c[mt][ni];
            const int r0 = crow0 + mt * 16;
            float b0 = bias[cc], b1 = bias[cc + 1];
            float2 v0 = { cf[0] + b0, cf[1] + b1 };
            float2 v1 = { cf[2] + b0, cf[3] + b1 };
            *reinterpret_cast<float2*>(C + (size_t)r0 * DIM + cc) = v0;
            *reinterpret_cast<float2*>(C + (size_t)(r0 + 8) * DIM + cc) = v1;
        }
    }
}

// ---------------------------------------------------------------------------
// Fused attention (1-term Q): QK + softmax + attn write + AV.
// CTA: 64 q rows, 128 threads (4 warps); warp = 16 q rows x 256 tokens.
// ---------------------------------------------------------------------------
#define FA_PAD 144
#define FA_Q  0
#define FA_K  (64 * FA_PAD)               // 9216
#define FA_V  (FA_K + 256 * FA_PAD)       // 46080
#define FA_SMEM (FA_V + 256 * FA_PAD)     // 82944

__global__ __launch_bounds__(128, 2)
void fused_attn_kernel(const __half* __restrict__ Qh,
                       const __half* __restrict__ Kh, const __half* __restrict__ Vh,
                       float* __restrict__ attnF, __half* __restrict__ Oh,
                       int writeAttn) {
    extern __shared__ char smem[];
    const uint32_t sb = smem_u32(smem);
    const int bh = blockIdx.y;
    const int q0 = blockIdx.x * 64;
    const int tid  = threadIdx.x;
    const int lane = tid & 31;
    const int wid  = tid >> 5;

    const __half* gQh = Qh + ((size_t)bh * NMM + q0) * HD;
    const __half* gKh = Kh + (size_t)bh * NKV * HD;
    const __half* gVh = Vh + (size_t)bh * NKV * HD;

    for (int idx = tid; idx < 512; idx += 128) {
        int row = idx >> 3, cq = idx & 7;
        cp_async16(sb + FA_Q + row * FA_PAD + cq * 16, gQh + row * HD + cq * 8);
    }
    for (int idx = tid; idx < 2048; idx += 128) {
        int row = idx >> 3, cq = idx & 7;
        cp_async16(sb + FA_K + row * FA_PAD + cq * 16, gKh + row * HD + cq * 8);
    }
    cp_commit();
    for (int idx = tid; idx < 2048; idx += 128) {
        int row = idx >> 3, cq = idx & 7;
        cp_async16(sb + FA_V + row * FA_PAD + cq * 16, gVh + row * HD + cq * 8);
    }
    cp_commit();

    cp_wait<1>();
    __syncthreads();

    const int lr = lane & 15;
    const int lc16 = (lane >> 4) * 16;
    const int rowbase = wid * 16;

    float c[32][4];
    #pragma unroll
    for (int j = 0; j < 32; j++)
        #pragma unroll
        for (int k = 0; k < 4; k++) c[j][k] = 0.0f;

    #pragma unroll
    for (int kk = 0; kk < 4; kk++) {
        const uint32_t ko = kk * 32;
        uint32_t aH[4];
        const uint32_t ab = sb + FA_Q + (rowbase + lr) * FA_PAD + ko + lc16;
        ldsm4(aH[0], aH[1], aH[2], aH[3], ab);
        #pragma unroll
        for (int tb = 0; tb < 16; tb++) {
            const uint32_t bb = sb + FA_K + (tb * 16 + lr) * FA_PAD + ko + lc16;
            uint32_t h0, h1, h2, h3;
            ldsm4(h0, h1, h2, h3, bb);
            mma16816(c[tb * 2],     aH, h0, h2);
            mma16816(c[tb * 2 + 1], aH, h1, h3);
        }
    }

    const float scale = 0.125f;
    #pragma unroll
    for (int s2 = 0; s2 < 2; s2++) {
        float m = -INFINITY;
        #pragma unroll
        for (int nt = 0; nt < 32; nt++) {
            m = fmaxf(m, c[nt][s2 * 2]);
            m = fmaxf(m, c[nt][s2 * 2 + 1]);
        }
        m = fmaxf(m, __shfl_xor_sync(0xffffffffu, m, 1));
        m = fmaxf(m, __shfl_xor_sync(0xffffffffu, m, 2));
        float sum = 0.0f;
        #pragma unroll
        for (int nt = 0; nt < 32; nt++) {
            float e0 = __expf((c[nt][s2 * 2]     - m) * scale);
            float e1 = __expf((c[nt][s2 * 2 + 1] - m) * scale);
            c[nt][s2 * 2]     = e0;
            c[nt][s2 * 2 + 1] = e1;
            sum += e0 + e1;
        }
        sum += __shfl_xor_sync(0xffffffffu, sum, 1);
        sum += __shfl_xor_sync(0xffffffffu, sum, 2);
        float inv = 1.0f / sum;
        #pragma unroll
        for (int nt = 0; nt < 32; nt++) {
            c[nt][s2 * 2]     *= inv;
            c[nt][s2 * 2 + 1] *= inv;
        }
    }

    if (writeAttn) {
        const int r  = lane >> 2;
        const int c0 = (lane & 3) * 2;
        float* rowp0 = attnF + ((size_t)bh * NMM + q0 + rowbase + r)     * NKV + c0;
        float* rowp1 = attnF + ((size_t)bh * NMM + q0 + rowbase + r + 8) * NKV + c0;
        #pragma unroll
        for (int nt = 0; nt < 32; nt++) {
            float2 v0 = { c[nt][0], c[nt][1] };
            float2 v1 = { c[nt][2], c[nt][3] };
            *reinterpret_cast<float2*>(rowp0 + nt * 8) = v0;
            *reinterpret_cast<float2*>(rowp1 + nt * 8) = v1;
        }
    }

    cp_wait<0>();
    __syncthreads();

    float o[8][4];
    #pragma unroll
    for (int j = 0; j < 8; j++)
        #pragma unroll
        for (int k = 0; k < 4; k++) o[j][k] = 0.0f;

    #pragma unroll
    for (int kt = 0; kt < 16; kt++) {
        uint32_t a[4];
        a[0] = pack_h(c[2 * kt][0],     c[2 * kt][1]);
        a[1] = pack_h(c[2 * kt][2],     c[2 * kt][3]);
        a[2] = pack_h(c[2 * kt + 1][0], c[2 * kt + 1][1]);
        a[3] = pack_h(c[2 * kt + 1][2], c[2 * kt + 1][3]);
        #pragma unroll
        for (int dblk = 0; dblk < 4; dblk++) {
            uint32_t v0, v1, v2, v3;
            const uint32_t vb = sb + FA_V + (kt * 16 + lr) * FA_PAD + dblk * 32 + lc16;
            ldsm4t(v0, v1, v2, v3, vb);
            mma16816(o[dblk * 2],     a, v0, v1);
            mma16816(o[dblk * 2 + 1], a, v2, v3);
        }
    }

    const int b = bh / HEADS, h = bh % HEADS;
    const int r = lane >> 2;
    #pragma unroll
    for (int j = 0; j < 8; j++) {
        const int d = j * 8 + (lane & 3) * 2;
        #pragma unroll
        for (int s = 0; s < 2; s++) {
            const int q = q0 + rowbase + r + s * 8;
            size_t idx = ((size_t)(b * NMM + q)) * DIM + h * HD + d;
            *reinterpret_cast<uint32_t*>(Oh + idx) = pack_h(o[j][s * 2], o[j][s * 2 + 1]);
        }
    }
}

// ---------------------------------------------------------------------------
// Launch
// ---------------------------------------------------------------------------
extern "C" void kernel_launch(void* const* d_in, const int* in_sizes, int n_in,
                              void* d_out, int out_size) {
    const float* xmm   = (const float*)d_in[0];
    const float* xv    = (const float*)d_in[1];
    const float* xa    = (const float*)d_in[2];
    const float* Wq    = (const float*)d_in[3];
    const float* Wkv   = (const float*)d_in[4];
    const float* Wproj = (const float*)d_in[5];
    const float* bproj = (const float*)d_in[6];
    float* out = (float*)d_out;

    __half *xmm_h, *xsrc_h;
    __half *WqT_h, *WkvT_h, *WpT_h;
    __half *Qh, *Kh, *Vh, *Oh;
    float* attn_fb;
    cudaGetSymbolAddress((void**)&xmm_h,  g_xmm_h);
    cudaGetSymbolAddress((void**)&xsrc_h, g_xsrc_h);
    cudaGetSymbolAddress((void**)&WqT_h,  g_WqT_h);
    cudaGetSymbolAddress((void**)&WkvT_h, g_WkvT_h);
    cudaGetSymbolAddress((void**)&WpT_h,  g_WpT_h);
    cudaGetSymbolAddress((void**)&Qh,  g_Qh);
    cudaGetSymbolAddress((void**)&Kh,  g_Kh);
    cudaGetSymbolAddress((void**)&Vh,  g_Vh);
    cudaGetSymbolAddress((void**)&Oh,  g_Oh);
    cudaGetSymbolAddress((void**)&attn_fb, g_attn_fallback);

    const int writeAttn = (out_size >= (OUT_ELEMS + ATTN_ELEMS)) ? 1 : 0;
    float* attn = writeAttn ? (out + OUT_ELEMS) : attn_fb;

    cudaFuncSetAttribute(qkv_proj_kernel, cudaFuncAttributeMaxDynamicSharedMemorySize, GEMM_SMEM);
    cudaFuncSetAttribute(out_proj_kernel, cudaFuncAttributeMaxDynamicSharedMemorySize, GEMM_SMEM);
    cudaFuncSetAttribute(fused_attn_kernel, cudaFuncAttributeMaxDynamicSharedMemorySize, FA_SMEM);

    // 1) input rounding + weight transposes, one launch
    prep_all_kernel<<<PREP_BLOCKS + TR_BLOCKS, 256>>>(
        (const float4*)xmm, xv, xa,
        (uint2*)xmm_h, (uint2*)xsrc_h,
        Wq, Wkv, Wproj, WqT_h, WkvT_h, WpT_h);

    // 2) merged Q + KV projections (all 1-term)
    qkv_proj_kernel<<<dim3(18, M_ROWS / 128), 256, GEMM_SMEM>>>(
        xmm_h, WqT_h, xsrc_h, WkvT_h, Qh, Kh, Vh);

    // 3) fused QK + softmax + attn write + AV (1-term Q)
    fused_attn_kernel<<<dim3(NMM / 64, NBH), 128, FA_SMEM>>>(
        Qh, Kh, Vh, attn, Oh, writeAttn);

    // 4) out-proj
    out_proj_kernel<<<dim3(6, M_ROWS / 128), 256, GEMM_SMEM>>>(
        Oh, WpT_h, bproj, out);
}